// round 1
// baseline (speedup 1.0000x reference)
#include <cuda_runtime.h>
#include <cuda_bf16.h>
#include <math.h>

#define NN   1024
#define DD   256
#define HH   128
#define BN_EPS 1e-5f

// ---------------- scratch (device globals; no allocation) ----------------
__device__ float g_a[NN * HH];     // X @ W1[:D] + b1
__device__ float g_c[NN * HH];     // X @ W1[D:]
__device__ float g_y[NN * HH];     // X @ Wg
__device__ float g_W[NN * NN];     // adjacency weights (symmetric, diag=1)
__device__ float g_dis[NN];        // rsqrt(deg)
__device__ float g_z[NN * HH];     // dis[j] * y[j]
__device__ float g_raw[NN * HH];   // dis[i]*(W@Z)[i] + bg  (pre-BN)
__device__ float g_sum[HH];
__device__ float g_sumsq[HH];

// ---------------- K1: fused 3x GEMM  C[1024,128] = X[1024,256] @ B[256,128]
// grid (64, 3): 64 M-blocks of TM=16 rows, z selects {W1a(+b1), W1c, Wg}.
// 256 threads: h = t&127, row-half = t>>7 (8 rows each). BK=32, 8 chunks.
__global__ __launch_bounds__(256, 4)
void k1_gemm3(const float* __restrict__ X, const float* __restrict__ W1,
              const float* __restrict__ Wg, const float* __restrict__ b1) {
    const int z  = blockIdx.y;
    const int i0 = blockIdx.x * 16;
    const int t  = threadIdx.x;
    const int h  = t & 127;
    const int rbase = (t >> 7) * 8;

    // one-time zero of BN accumulators (any early kernel works; stream-ordered)
    if (blockIdx.x == 0 && z == 0) {
        if (t < 128) g_sum[t] = 0.f;
        else if (t < 256) g_sumsq[t - 128] = 0.f;
    }

    const float* B = (z == 0) ? W1 : (z == 1) ? (W1 + DD * HH) : Wg;

    __shared__ float Bs[32][128];    // natural layout: b = Bs[kk][h]
    __shared__ float Xst[32][20];    // transposed X tile, padded

    float acc[8];
    #pragma unroll
    for (int r = 0; r < 8; r++) acc[r] = 0.f;

    for (int c = 0; c < 8; c++) {
        const int k0 = c * 32;
        // load B tile: 32x128 = 4096 floats, 4 x float4 per thread
        #pragma unroll
        for (int p = 0; p < 4; p++) {
            int pos = t * 4 + p * 1024;
            int kk = pos >> 7, hh = pos & 127;
            *(float4*)&Bs[kk][hh] = *(const float4*)&B[(k0 + kk) * HH + hh];
        }
        // load X tile transposed: 16 rows x 32 k
        #pragma unroll
        for (int p = 0; p < 2; p++) {
            int kk = t & 31;
            int r  = (t >> 5) + p * 8;
            Xst[kk][r] = X[(i0 + r) * DD + k0 + kk];
        }
        __syncthreads();
        #pragma unroll
        for (int kk = 0; kk < 32; kk++) {
            float b = Bs[kk][h];
            float4 xa = *(const float4*)&Xst[kk][rbase];
            float4 xb = *(const float4*)&Xst[kk][rbase + 4];
            acc[0] = fmaf(xa.x, b, acc[0]);
            acc[1] = fmaf(xa.y, b, acc[1]);
            acc[2] = fmaf(xa.z, b, acc[2]);
            acc[3] = fmaf(xa.w, b, acc[3]);
            acc[4] = fmaf(xb.x, b, acc[4]);
            acc[5] = fmaf(xb.y, b, acc[5]);
            acc[6] = fmaf(xb.z, b, acc[6]);
            acc[7] = fmaf(xb.w, b, acc[7]);
        }
        __syncthreads();
    }

    float bias = (z == 0) ? b1[h] : 0.f;
    float* dst = (z == 0) ? g_a : (z == 1) ? g_c : g_y;
    #pragma unroll
    for (int r = 0; r < 8; r++) {
        int i = i0 + rbase + r;
        dst[i * HH + h] = acc[r] + bias;
    }
}

// ---------------- K2: pairwise sim on upper-triangle 32x32 tiles ----------
// 528 blocks, 256 threads, each thread a 2x2 pair sub-tile.
__global__ __launch_bounds__(256, 4)
void k2_pairwise(const float* __restrict__ W2, const float* __restrict__ b2) {
    // decode linear tile index -> (ti, tj), ti <= tj
    int rem = blockIdx.x;
    int ti = 0;
    #pragma unroll 1
    while (rem >= (32 - ti)) { rem -= (32 - ti); ti++; }
    const int tj = ti + rem;
    const int i0 = ti * 32, j0 = tj * 32;
    const int t = threadIdx.x;

    __shared__ float As[32][132];
    __shared__ float Cs[32][132];
    __shared__ float W2s[128];

    if (t < 128) W2s[t] = W2[t];
    #pragma unroll
    for (int p = 0; p < 4; p++) {
        int pos = t * 4 + p * 1024;
        int row = pos >> 7, h = pos & 127;
        *(float4*)&As[row][h] = *(const float4*)&g_a[(i0 + row) * HH + h];
        *(float4*)&Cs[row][h] = *(const float4*)&g_c[(j0 + row) * HH + h];
    }
    __syncthreads();

    const int iq = t >> 4;      // 0..15
    const int jq = t & 15;      // 0..15
    const int i2 = iq * 2, j2 = jq * 2;

    float a00 = 0.f, a01 = 0.f, a10 = 0.f, a11 = 0.f;

    #pragma unroll 4
    for (int h = 0; h < 128; h += 4) {
        float4 w4 = *(const float4*)&W2s[h];
        float4 r0 = *(const float4*)&As[i2][h];
        float4 r1 = *(const float4*)&As[i2 + 1][h];
        float4 c0 = *(const float4*)&Cs[j2][h];
        float4 c1 = *(const float4*)&Cs[j2 + 1][h];
        a00 = fmaf(fmaxf(r0.x + c0.x, 0.f), w4.x, a00);
        a00 = fmaf(fmaxf(r0.y + c0.y, 0.f), w4.y, a00);
        a00 = fmaf(fmaxf(r0.z + c0.z, 0.f), w4.z, a00);
        a00 = fmaf(fmaxf(r0.w + c0.w, 0.f), w4.w, a00);
        a01 = fmaf(fmaxf(r0.x + c1.x, 0.f), w4.x, a01);
        a01 = fmaf(fmaxf(r0.y + c1.y, 0.f), w4.y, a01);
        a01 = fmaf(fmaxf(r0.z + c1.z, 0.f), w4.z, a01);
        a01 = fmaf(fmaxf(r0.w + c1.w, 0.f), w4.w, a01);
        a10 = fmaf(fmaxf(r1.x + c0.x, 0.f), w4.x, a10);
        a10 = fmaf(fmaxf(r1.y + c0.y, 0.f), w4.y, a10);
        a10 = fmaf(fmaxf(r1.z + c0.z, 0.f), w4.z, a10);
        a10 = fmaf(fmaxf(r1.w + c0.w, 0.f), w4.w, a10);
        a11 = fmaf(fmaxf(r1.x + c1.x, 0.f), w4.x, a11);
        a11 = fmaf(fmaxf(r1.y + c1.y, 0.f), w4.y, a11);
        a11 = fmaf(fmaxf(r1.z + c1.z, 0.f), w4.z, a11);
        a11 = fmaf(fmaxf(r1.w + c1.w, 0.f), w4.w, a11);
    }

    const float b2v = b2[0];
    float accs[2][2] = {{a00, a01}, {a10, a11}};
    #pragma unroll
    for (int r = 0; r < 2; r++) {
        #pragma unroll
        for (int s = 0; s < 2; s++) {
            int i = i0 + i2 + r;
            int j = j0 + j2 + s;
            float x = accs[r][s] + b2v;
            if (i < j) {
                float sg = 1.f / (1.f + __expf(-x));
                float w = (x > 0.f) ? sg : 0.f;
                g_W[i * NN + j] = w;
                g_W[j * NN + i] = w;
            } else if (i == j) {
                g_W[i * NN + i] = 1.0f;
            }
        }
    }
}

// ---------------- K3: deg -> dis -> Z ------------------------------------
__global__ __launch_bounds__(256, 4)
void k3_degree() {
    const int i = blockIdx.x;
    const int t = threadIdx.x;
    float4 v = *(const float4*)&g_W[i * NN + t * 4];
    float s = v.x + v.y + v.z + v.w;
    // warp + smem reduce
    #pragma unroll
    for (int o = 16; o > 0; o >>= 1) s += __shfl_down_sync(0xffffffffu, s, o);
    __shared__ float red[8];
    if ((t & 31) == 0) red[t >> 5] = s;
    __syncthreads();
    if (t < 32) {
        float r = (t < 8) ? red[t] : 0.f;
        #pragma unroll
        for (int o = 4; o > 0; o >>= 1) r += __shfl_down_sync(0xffffffffu, r, o);
        if (t == 0) red[0] = r;
    }
    __syncthreads();
    float dis = rsqrtf(red[0]);
    if (t == 0) g_dis[i] = dis;
    if (t < 128) g_z[i * HH + t] = dis * g_y[i * HH + t];
}

// ---------------- K4: raw = dis[i]*(W @ Z) + bg --------------------------
// grid 128 (TM=8), 256 threads: two k-groups of 128 (k halves), combine.
__global__ __launch_bounds__(256, 4)
void k4_aggregate(const float* __restrict__ bg) {
    const int i0 = blockIdx.x * 8;
    const int t  = threadIdx.x;
    const int g  = t >> 7;        // k-half
    const int h  = t & 127;

    __shared__ float Zs[2][32][128];   // 32 KB
    __shared__ float Wst[2][32][12];   // transposed W tile, padded
    __shared__ float partial[128 * 8]; // 4 KB

    float acc[8];
    #pragma unroll
    for (int r = 0; r < 8; r++) acc[r] = 0.f;

    for (int c = 0; c < 16; c++) {
        const int k0 = g * 512 + c * 32;
        #pragma unroll
        for (int p = 0; p < 8; p++) {
            int pos = h * 4 + p * 512;
            int kk = pos >> 7, hh = pos & 127;
            *(float4*)&Zs[g][kk][hh] = *(const float4*)&g_z[(k0 + kk) * HH + hh];
        }
        #pragma unroll
        for (int p = 0; p < 2; p++) {
            int idx = h + p * 128;
            int r = idx >> 5, kk = idx & 31;
            Wst[g][kk][r] = g_W[(i0 + r) * NN + k0 + kk];
        }
        __syncthreads();
        #pragma unroll 8
        for (int kk = 0; kk < 32; kk++) {
            float zv = Zs[g][kk][h];
            float4 wa = *(const float4*)&Wst[g][kk][0];
            float4 wb = *(const float4*)&Wst[g][kk][4];
            acc[0] = fmaf(wa.x, zv, acc[0]);
            acc[1] = fmaf(wa.y, zv, acc[1]);
            acc[2] = fmaf(wa.z, zv, acc[2]);
            acc[3] = fmaf(wa.w, zv, acc[3]);
            acc[4] = fmaf(wb.x, zv, acc[4]);
            acc[5] = fmaf(wb.y, zv, acc[5]);
            acc[6] = fmaf(wb.z, zv, acc[6]);
            acc[7] = fmaf(wb.w, zv, acc[7]);
        }
        __syncthreads();
    }

    if (g == 1) {
        #pragma unroll
        for (int r = 0; r < 8; r++) partial[h * 8 + r] = acc[r];
    }
    __syncthreads();
    if (g == 0) {
        float bgv = bg[h];
        #pragma unroll
        for (int r = 0; r < 8; r++) {
            int i = i0 + r;
            float v = (acc[r] + partial[h * 8 + r]) * g_dis[i] + bgv;
            g_raw[i * HH + h] = v;
        }
    }
}

// ---------------- K5: BN stats (atomics into g_sum/g_sumsq) --------------
__global__ __launch_bounds__(256, 4)
void k5_stats() {
    const int t = threadIdx.x;
    const int h = t & 127;
    const int half = t >> 7;
    const int ib = blockIdx.x * 16 + half * 8;
    float s = 0.f, s2 = 0.f;
    #pragma unroll
    for (int r = 0; r < 8; r++) {
        float v = g_raw[(ib + r) * HH + h];
        s += v;
        s2 = fmaf(v, v, s2);
    }
    atomicAdd(&g_sum[h], s);
    atomicAdd(&g_sumsq[h], s2);
}

// ---------------- K6: normalize + relu -> d_out --------------------------
__global__ __launch_bounds__(256, 4)
void k6_norm(const float* __restrict__ gamma, const float* __restrict__ beta,
             float* __restrict__ out) {
    const int idx = blockIdx.x * 256 + threadIdx.x;
    const int h = idx & 127;
    const float inv_n = 1.f / (float)NN;
    float mean = g_sum[h] * inv_n;
    float var = g_sumsq[h] * inv_n - mean * mean;
    float x = g_raw[idx];
    float v = gamma[h] * (x - mean) * rsqrtf(var + BN_EPS) + beta[h];
    out[idx] = fmaxf(v, 0.f);
}

// ---------------- launch -------------------------------------------------
extern "C" void kernel_launch(void* const* d_in, const int* in_sizes, int n_in,
                              void* d_out, int out_size) {
    const float* X     = (const float*)d_in[0];
    const float* W1    = (const float*)d_in[1];
    const float* b1    = (const float*)d_in[2];
    const float* W2    = (const float*)d_in[3];
    const float* b2    = (const float*)d_in[4];
    const float* Wg    = (const float*)d_in[5];
    const float* bg    = (const float*)d_in[6];
    const float* gamma = (const float*)d_in[7];
    const float* beta  = (const float*)d_in[8];
    float* out = (float*)d_out;

    k1_gemm3<<<dim3(64, 3), 256>>>(X, W1, Wg, b1);
    k2_pairwise<<<528, 256>>>(W2, b2);
    k3_degree<<<1024, 256>>>();
    k4_aggregate<<<128, 256>>>(bg);
    k5_stats<<<64, 256>>>();
    k6_norm<<<512, 256>>>(gamma, beta, out);
}

// round 2
// speedup vs baseline: 1.1462x; 1.1462x over previous
#include <cuda_runtime.h>
#include <cuda_bf16.h>
#include <math.h>

#define NN   1024
#define DD   256
#define HH   128
#define KSPLIT 8
#define BN_EPS 1e-5f

// ---------------- scratch (device globals; no allocation) ----------------
__device__ float g_a[NN * HH];            // X @ W1[:D] + b1
__device__ float g_c[NN * HH];            // X @ W1[D:]
__device__ float g_y[NN * HH];            // X @ Wg
__device__ float g_W[NN * NN];            // adjacency weights (symmetric, diag=1)
__device__ float g_dis[NN];               // rsqrt(deg)
__device__ float g_z[NN * HH];            // dis[j] * y[j]
__device__ float g_part[KSPLIT * NN * HH];// split-K partials of W@Z
__device__ float g_raw[NN * HH];          // dis[i]*(W@Z)[i] + bg  (pre-BN)
__device__ float g_sum[HH];
__device__ float g_sumsq[HH];

// packed f32x2 helpers (ptxas will not fuse these from C++)
#define F2LL(x) (*reinterpret_cast<unsigned long long*>(&(x)))
__device__ __forceinline__ float2 fadd2(float2 a, float2 b) {
    float2 r;
    asm("add.rn.f32x2 %0, %1, %2;" : "=l"(F2LL(r)) : "l"(F2LL(a)), "l"(F2LL(b)));
    return r;
}
__device__ __forceinline__ void ffma2(float2& acc, float2 a, float2 b) {
    asm("fma.rn.f32x2 %0, %1, %2, %0;" : "+l"(F2LL(acc)) : "l"(F2LL(a)), "l"(F2LL(b)));
}

// ---------------- K1: fused 3x GEMM  C[1024,128] = X[1024,256] @ B[256,128]
__global__ __launch_bounds__(256, 4)
void k1_gemm3(const float* __restrict__ X, const float* __restrict__ W1,
              const float* __restrict__ Wg, const float* __restrict__ b1) {
    const int z  = blockIdx.y;
    const int i0 = blockIdx.x * 16;
    const int t  = threadIdx.x;
    const int h  = t & 127;
    const int rbase = (t >> 7) * 8;

    if (blockIdx.x == 0 && z == 0) {
        if (t < 128) g_sum[t] = 0.f;
        else if (t < 256) g_sumsq[t - 128] = 0.f;
    }

    const float* B = (z == 0) ? W1 : (z == 1) ? (W1 + DD * HH) : Wg;

    __shared__ float Bs[32][128];
    __shared__ float Xst[32][20];

    float acc[8];
    #pragma unroll
    for (int r = 0; r < 8; r++) acc[r] = 0.f;

    for (int c = 0; c < 8; c++) {
        const int k0 = c * 32;
        #pragma unroll
        for (int p = 0; p < 4; p++) {
            int pos = t * 4 + p * 1024;
            int kk = pos >> 7, hh = pos & 127;
            *(float4*)&Bs[kk][hh] = *(const float4*)&B[(k0 + kk) * HH + hh];
        }
        #pragma unroll
        for (int p = 0; p < 2; p++) {
            int kk = t & 31;
            int r  = (t >> 5) + p * 8;
            Xst[kk][r] = X[(i0 + r) * DD + k0 + kk];
        }
        __syncthreads();
        #pragma unroll
        for (int kk = 0; kk < 32; kk++) {
            float b = Bs[kk][h];
            float4 xa = *(const float4*)&Xst[kk][rbase];
            float4 xb = *(const float4*)&Xst[kk][rbase + 4];
            acc[0] = fmaf(xa.x, b, acc[0]);
            acc[1] = fmaf(xa.y, b, acc[1]);
            acc[2] = fmaf(xa.z, b, acc[2]);
            acc[3] = fmaf(xa.w, b, acc[3]);
            acc[4] = fmaf(xb.x, b, acc[4]);
            acc[5] = fmaf(xb.y, b, acc[5]);
            acc[6] = fmaf(xb.z, b, acc[6]);
            acc[7] = fmaf(xb.w, b, acc[7]);
        }
        __syncthreads();
    }

    float bias = (z == 0) ? b1[h] : 0.f;
    float* dst = (z == 0) ? g_a : (z == 1) ? g_c : g_y;
    #pragma unroll
    for (int r = 0; r < 8; r++) {
        int i = i0 + rbase + r;
        dst[i * HH + h] = acc[r] + bias;
    }
}

// ---------------- K2: pairwise sim, 64x64 upper-triangle tiles -----------
// 136 blocks, 256 threads, 4x4 register tile per thread, packed f32x2 math.
// smem held as float2 with row stride 65 float2 (=130 floats): odd stride in
// float2 units -> conflict-free strided-row reads.
__global__ __launch_bounds__(256, 1)
void k2_pairwise(const float* __restrict__ W2, const float* __restrict__ b2) {
    int rem = blockIdx.x;
    int ti = 0;
    #pragma unroll 1
    while (rem >= (16 - ti)) { rem -= (16 - ti); ti++; }
    const int tj = ti + rem;
    const int i0 = ti * 64, j0 = tj * 64;
    const int t = threadIdx.x;

    __shared__ float2 As2[64 * 65];
    __shared__ float2 Cs2[64 * 65];
    __shared__ float2 W2s2[64];

    if (t < 64) W2s2[t] = ((const float2*)W2)[t];
    const float2* ga2 = (const float2*)g_a;
    const float2* gc2 = (const float2*)g_c;
    #pragma unroll
    for (int p = 0; p < 16; p++) {
        int idx = t + p * 256;              // 0..4095
        int row = idx >> 6, h2 = idx & 63;
        As2[row * 65 + h2] = ga2[(i0 + row) * 64 + h2];
        Cs2[row * 65 + h2] = gc2[(j0 + row) * 64 + h2];
    }
    __syncthreads();

    const int iq = t >> 4;      // 0..15 -> rows iq + {0,16,32,48}
    const int jq = t & 15;      // 0..15 -> cols jq + {0,16,32,48}

    float2 acc[4][4];
    #pragma unroll
    for (int r = 0; r < 4; r++)
        #pragma unroll
        for (int s = 0; s < 4; s++) acc[r][s] = make_float2(0.f, 0.f);

    #pragma unroll 4
    for (int h2 = 0; h2 < 64; h2++) {
        float2 w = W2s2[h2];
        float2 a[4], c[4];
        #pragma unroll
        for (int r = 0; r < 4; r++) a[r] = As2[(iq + r * 16) * 65 + h2];
        #pragma unroll
        for (int s = 0; s < 4; s++) c[s] = Cs2[(jq + s * 16) * 65 + h2];
        #pragma unroll
        for (int r = 0; r < 4; r++) {
            #pragma unroll
            for (int s = 0; s < 4; s++) {
                float2 v = fadd2(a[r], c[s]);      // fma pipe (packed)
                v.x = fmaxf(v.x, 0.f);             // alu pipe
                v.y = fmaxf(v.y, 0.f);             // alu pipe
                ffma2(acc[r][s], v, w);            // fma pipe (packed)
            }
        }
    }

    const float b2v = b2[0];
    #pragma unroll
    for (int r = 0; r < 4; r++) {
        #pragma unroll
        for (int s = 0; s < 4; s++) {
            int i = i0 + iq + r * 16;
            int j = j0 + jq + s * 16;
            float x = acc[r][s].x + acc[r][s].y + b2v;
            if (i < j) {
                float sg = 1.f / (1.f + __expf(-x));
                float w = (x > 0.f) ? sg : 0.f;
                g_W[i * NN + j] = w;
                g_W[j * NN + i] = w;
            } else if (i == j) {
                g_W[i * NN + i] = 1.0f;
            }
        }
    }
}

// ---------------- K3: deg -> dis -> Z ------------------------------------
__global__ __launch_bounds__(256, 4)
void k3_degree() {
    const int i = blockIdx.x;
    const int t = threadIdx.x;
    float4 v = *(const float4*)&g_W[i * NN + t * 4];
    float s = v.x + v.y + v.z + v.w;
    #pragma unroll
    for (int o = 16; o > 0; o >>= 1) s += __shfl_down_sync(0xffffffffu, s, o);
    __shared__ float red[8];
    if ((t & 31) == 0) red[t >> 5] = s;
    __syncthreads();
    if (t < 32) {
        float r = (t < 8) ? red[t] : 0.f;
        #pragma unroll
        for (int o = 4; o > 0; o >>= 1) r += __shfl_down_sync(0xffffffffu, r, o);
        if (t == 0) red[0] = r;
    }
    __syncthreads();
    float dis = rsqrtf(red[0]);
    if (t == 0) g_dis[i] = dis;
    if (t < 128) g_z[i * HH + t] = dis * g_y[i * HH + t];
}

// ---------------- K4: split-K partials of W @ Z --------------------------
// grid (64, 8): BM=16 rows, each block covers k-range of 128 (4 x BK=32).
// 256 threads: h = t&127, half = t>>7 handles 8 rows.
__global__ __launch_bounds__(256, 4)
void k4_aggregate() {
    const int i0 = blockIdx.x * 16;
    const int ks = blockIdx.y;
    const int t  = threadIdx.x;
    const int h  = t & 127;
    const int rbase = (t >> 7) * 8;

    __shared__ float Zs[32][128];   // 16 KB
    __shared__ float Wst[32][20];   // transposed W tile (16 rows + pad)

    float acc[8];
    #pragma unroll
    for (int r = 0; r < 8; r++) acc[r] = 0.f;

    #pragma unroll 1
    for (int c = 0; c < 4; c++) {
        const int k0 = ks * 128 + c * 32;
        #pragma unroll
        for (int p = 0; p < 4; p++) {
            int pos = t * 4 + p * 1024;
            int kk = pos >> 7, hh = pos & 127;
            *(float4*)&Zs[kk][hh] = *(const float4*)&g_z[(k0 + kk) * HH + hh];
        }
        #pragma unroll
        for (int p = 0; p < 2; p++) {
            int idx = t + p * 256;
            int r = idx >> 5, kk = idx & 31;
            Wst[kk][r] = g_W[(i0 + r) * NN + k0 + kk];
        }
        __syncthreads();
        #pragma unroll 8
        for (int kk = 0; kk < 32; kk++) {
            float zv = Zs[kk][h];
            float4 wa = *(const float4*)&Wst[kk][rbase];
            float4 wb = *(const float4*)&Wst[kk][rbase + 4];
            acc[0] = fmaf(wa.x, zv, acc[0]);
            acc[1] = fmaf(wa.y, zv, acc[1]);
            acc[2] = fmaf(wa.z, zv, acc[2]);
            acc[3] = fmaf(wa.w, zv, acc[3]);
            acc[4] = fmaf(wb.x, zv, acc[4]);
            acc[5] = fmaf(wb.y, zv, acc[5]);
            acc[6] = fmaf(wb.z, zv, acc[6]);
            acc[7] = fmaf(wb.w, zv, acc[7]);
        }
        __syncthreads();
    }

    #pragma unroll
    for (int r = 0; r < 8; r++)
        g_part[(ks * NN + i0 + rbase + r) * HH + h] = acc[r];
}

// ---------------- K5: reduce partials + dis/bg epilogue + BN stats -------
__global__ __launch_bounds__(256, 4)
void k5_stats(const float* __restrict__ bg) {
    const int t = threadIdx.x;
    const int h = t & 127;
    const int half = t >> 7;
    const int ib = blockIdx.x * 16 + half * 8;
    const float bgv = bg[h];
    float s = 0.f, s2 = 0.f;
    #pragma unroll
    for (int r = 0; r < 8; r++) {
        int i = ib + r;
        int idx = i * HH + h;
        float v = 0.f;
        #pragma unroll
        for (int ks = 0; ks < KSPLIT; ks++) v += g_part[ks * NN * HH + idx];
        v = v * g_dis[i] + bgv;
        g_raw[idx] = v;
        s += v;
        s2 = fmaf(v, v, s2);
    }
    atomicAdd(&g_sum[h], s);
    atomicAdd(&g_sumsq[h], s2);
}

// ---------------- K6: normalize + relu -> d_out --------------------------
__global__ __launch_bounds__(256, 4)
void k6_norm(const float* __restrict__ gamma, const float* __restrict__ beta,
             float* __restrict__ out) {
    const int idx = blockIdx.x * 256 + threadIdx.x;
    const int h = idx & 127;
    const float inv_n = 1.f / (float)NN;
    float mean = g_sum[h] * inv_n;
    float var = g_sumsq[h] * inv_n - mean * mean;
    float x = g_raw[idx];
    float v = gamma[h] * (x - mean) * rsqrtf(var + BN_EPS) + beta[h];
    out[idx] = fmaxf(v, 0.f);
}

// ---------------- launch -------------------------------------------------
extern "C" void kernel_launch(void* const* d_in, const int* in_sizes, int n_in,
                              void* d_out, int out_size) {
    const float* X     = (const float*)d_in[0];
    const float* W1    = (const float*)d_in[1];
    const float* b1    = (const float*)d_in[2];
    const float* W2    = (const float*)d_in[3];
    const float* b2    = (const float*)d_in[4];
    const float* Wg    = (const float*)d_in[5];
    const float* bg    = (const float*)d_in[6];
    const float* gamma = (const float*)d_in[7];
    const float* beta  = (const float*)d_in[8];
    float* out = (float*)d_out;

    k1_gemm3<<<dim3(64, 3), 256>>>(X, W1, Wg, b1);
    k2_pairwise<<<136, 256>>>(W2, b2);
    k3_degree<<<1024, 256>>>();
    k4_aggregate<<<dim3(64, KSPLIT), 256>>>();
    k5_stats<<<64, 256>>>(bg);
    k6_norm<<<512, 256>>>(gamma, beta, out);
}

// round 3
// speedup vs baseline: 1.3959x; 1.2179x over previous
#include <cuda_runtime.h>
#include <cuda_bf16.h>
#include <math.h>

#define NN   1024
#define DD   256
#define HH   128
#define KS1  4            // split-K for k1
#define KSPLIT 8          // split-K for k4
#define BN_EPS 1e-5f

// ---------------- scratch (device globals; no allocation) ----------------
__device__ float g_p1[3 * KS1 * NN * HH]; // k1 split-K partials (6 MB)
__device__ float g_a[NN * HH];            // X @ W1[:D] + b1
__device__ float g_c[NN * HH];            // X @ W1[D:]
__device__ float g_y[NN * HH];            // X @ Wg
__device__ float g_W[NN * NN];            // adjacency weights (symmetric, diag=1)
__device__ float g_dis[NN];               // rsqrt(deg)
__device__ float g_z[NN * HH];            // dis[j] * y[j]
__device__ float g_part[KSPLIT * NN * HH];// split-K partials of W@Z
__device__ float g_raw[NN * HH];          // dis[i]*(W@Z)[i] + bg  (pre-BN)
__device__ float g_sum[HH];
__device__ float g_sumsq[HH];

// packed f32x2 helpers
#define F2LL(x) (*reinterpret_cast<unsigned long long*>(&(x)))
__device__ __forceinline__ float2 fadd2(float2 a, float2 b) {
    float2 r;
    asm("add.rn.f32x2 %0, %1, %2;" : "=l"(F2LL(r)) : "l"(F2LL(a)), "l"(F2LL(b)));
    return r;
}
__device__ __forceinline__ void ffma2(float2& acc, float2 a, float2 b) {
    asm("fma.rn.f32x2 %0, %1, %2, %0;" : "+l"(F2LL(acc)) : "l"(F2LL(a)), "l"(F2LL(b)));
}

// ---------------- K1: split-K 3x GEMM partials ---------------------------
// grid (32, 3, KS1): 32-row blocks, z selects B matrix, bz = k-split.
// 256 threads: hq=t&31 -> h=hq*4 (4 cols), rq=t>>5 -> rows rq*4..+3.
// 4x4 micro-tile: 2 B/FMA smem traffic; X reads are warp-uniform broadcasts.
__global__ __launch_bounds__(256, 3)
void k1_gemm3(const float* __restrict__ X, const float* __restrict__ W1,
              const float* __restrict__ Wg) {
    const int z  = blockIdx.y;
    const int ks = blockIdx.z;
    const int i0 = blockIdx.x * 32;
    const int t  = threadIdx.x;
    const int hq = t & 31;
    const int rq = t >> 5;
    const int h  = hq * 4;

    if (blockIdx.x == 0 && z == 0 && ks == 0) {
        if (t < 128) g_sum[t] = 0.f;
        else g_sumsq[t - 128] = 0.f;
    }

    const float* B = (z == 0) ? W1 : (z == 1) ? (W1 + DD * HH) : Wg;

    __shared__ float Bs[32][128];
    __shared__ float Xst[32][36];

    float4 acc[4];
    #pragma unroll
    for (int r = 0; r < 4; r++) acc[r] = make_float4(0.f, 0.f, 0.f, 0.f);

    #pragma unroll
    for (int c = 0; c < 2; c++) {
        const int k0 = ks * 64 + c * 32;
        #pragma unroll
        for (int p = 0; p < 4; p++) {
            int pos = t * 4 + p * 1024;
            int kk = pos >> 7, hh = pos & 127;
            *(float4*)&Bs[kk][hh] = *(const float4*)&B[(k0 + kk) * HH + hh];
        }
        {
            int r = t >> 3, kkq = t & 7;
            float4 xv = *(const float4*)&X[(i0 + r) * DD + k0 + kkq * 4];
            Xst[kkq * 4 + 0][r] = xv.x;
            Xst[kkq * 4 + 1][r] = xv.y;
            Xst[kkq * 4 + 2][r] = xv.z;
            Xst[kkq * 4 + 3][r] = xv.w;
        }
        __syncthreads();
        #pragma unroll
        for (int kk = 0; kk < 32; kk++) {
            float4 b = *(const float4*)&Bs[kk][h];
            float4 x = *(const float4*)&Xst[kk][rq * 4];
            acc[0].x = fmaf(x.x, b.x, acc[0].x);
            acc[0].y = fmaf(x.x, b.y, acc[0].y);
            acc[0].z = fmaf(x.x, b.z, acc[0].z);
            acc[0].w = fmaf(x.x, b.w, acc[0].w);
            acc[1].x = fmaf(x.y, b.x, acc[1].x);
            acc[1].y = fmaf(x.y, b.y, acc[1].y);
            acc[1].z = fmaf(x.y, b.z, acc[1].z);
            acc[1].w = fmaf(x.y, b.w, acc[1].w);
            acc[2].x = fmaf(x.z, b.x, acc[2].x);
            acc[2].y = fmaf(x.z, b.y, acc[2].y);
            acc[2].z = fmaf(x.z, b.z, acc[2].z);
            acc[2].w = fmaf(x.z, b.w, acc[2].w);
            acc[3].x = fmaf(x.w, b.x, acc[3].x);
            acc[3].y = fmaf(x.w, b.y, acc[3].y);
            acc[3].z = fmaf(x.w, b.z, acc[3].z);
            acc[3].w = fmaf(x.w, b.w, acc[3].w);
        }
        __syncthreads();
    }

    float* dst = g_p1 + (z * KS1 + ks) * (NN * HH);
    #pragma unroll
    for (int r = 0; r < 4; r++)
        *(float4*)&dst[(i0 + rq * 4 + r) * HH + h] = acc[r];
}

// ---------------- K1R: reduce k1 partials (+b1 into g_a) -----------------
__global__ __launch_bounds__(256, 4)
void k1_reduce(const float* __restrict__ b1) {
    const int f = blockIdx.x * 256 + threadIdx.x;   // float4 index, 0..98303
    const int z = f >> 15;                          // 32768 float4 per z
    const int r = f & 32767;
    const float4* p = (const float4*)g_p1;
    float4 v = p[(z * KS1 + 0) * 32768 + r];
    #pragma unroll
    for (int ks = 1; ks < KS1; ks++) {
        float4 u = p[(z * KS1 + ks) * 32768 + r];
        v.x += u.x; v.y += u.y; v.z += u.z; v.w += u.w;
    }
    if (z == 0) {
        int h0 = (r * 4) & 127;
        v.x += b1[h0]; v.y += b1[h0 + 1]; v.z += b1[h0 + 2]; v.w += b1[h0 + 3];
    }
    float* dst = (z == 0) ? g_a : (z == 1) ? g_c : g_y;
    *(float4*)&dst[r * 4] = v;
}

// ---------------- K2: pairwise sim, 64x64 upper-triangle tiles -----------
// 136 blocks, 256 threads, 4x4 register tile of f32x2 pairs, coalesced
// dual-triangle stores via an smem-staged tile (aliased over As2).
__global__ __launch_bounds__(256, 1)
void k2_pairwise(const float* __restrict__ W2, const float* __restrict__ b2) {
    int rem = blockIdx.x;
    int ti = 0;
    #pragma unroll 1
    while (rem >= (16 - ti)) { rem -= (16 - ti); ti++; }
    const int tj = ti + rem;
    const int i0 = ti * 64, j0 = tj * 64;
    const int t = threadIdx.x;

    __shared__ float2 As2[64 * 65];
    __shared__ float2 Cs2[64 * 65];
    __shared__ float2 W2s2[64];

    if (t < 64) W2s2[t] = ((const float2*)W2)[t];
    const float2* ga2 = (const float2*)g_a;
    const float2* gc2 = (const float2*)g_c;
    #pragma unroll
    for (int p = 0; p < 16; p++) {
        int idx = t + p * 256;
        int row = idx >> 6, h2 = idx & 63;
        As2[row * 65 + h2] = ga2[(i0 + row) * 64 + h2];
        Cs2[row * 65 + h2] = gc2[(j0 + row) * 64 + h2];
    }
    __syncthreads();

    const int iq = t >> 4;
    const int jq = t & 15;

    float2 acc[4][4];
    #pragma unroll
    for (int r = 0; r < 4; r++)
        #pragma unroll
        for (int s = 0; s < 4; s++) acc[r][s] = make_float2(0.f, 0.f);

    #pragma unroll 4
    for (int h2 = 0; h2 < 64; h2++) {
        float2 w = W2s2[h2];
        float2 a[4], c[4];
        #pragma unroll
        for (int r = 0; r < 4; r++) a[r] = As2[(iq + r * 16) * 65 + h2];
        #pragma unroll
        for (int s = 0; s < 4; s++) c[s] = Cs2[(jq + s * 16) * 65 + h2];
        #pragma unroll
        for (int r = 0; r < 4; r++) {
            #pragma unroll
            for (int s = 0; s < 4; s++) {
                float2 v = fadd2(a[r], c[s]);
                v.x = fmaxf(v.x, 0.f);
                v.y = fmaxf(v.y, 0.f);
                ffma2(acc[r][s], v, w);
            }
        }
    }

    // stage tile in smem (alias over As2 storage; done reading it)
    __syncthreads();
    float* Ts = (float*)As2;        // used as [64][68]
    const float b2v = b2[0];
    const bool diag = (ti == tj);
    #pragma unroll
    for (int r = 0; r < 4; r++) {
        #pragma unroll
        for (int s = 0; s < 4; s++) {
            int il = iq + r * 16;
            int jl = jq + s * 16;
            float x = acc[r][s].x + acc[r][s].y + b2v;
            float sg = 1.f / (1.f + __expf(-x));
            float w = (x > 0.f) ? sg : 0.f;
            if (!diag) {
                Ts[il * 68 + jl] = w;
            } else {
                if (il < jl) {
                    Ts[il * 68 + jl] = w;
                    Ts[jl * 68 + il] = w;
                } else if (il == jl) {
                    Ts[il * 68 + il] = 1.0f;
                }
            }
        }
    }
    __syncthreads();

    // pass 1: rows i0..i0+63, cols j0..j0+63 (coalesced float4)
    #pragma unroll
    for (int p = 0; p < 4; p++) {
        int idx = t + p * 256;
        int row = idx >> 4, c4 = idx & 15;
        float4 v = *(const float4*)&Ts[row * 68 + c4 * 4];
        *(float4*)&g_W[(i0 + row) * NN + j0 + c4 * 4] = v;
    }
    // pass 2 (off-diag only): transposed triangle, coalesced float4
    if (!diag) {
        #pragma unroll
        for (int p = 0; p < 4; p++) {
            int idx = t + p * 256;
            int jr = idx >> 4, c4 = idx & 15;
            float4 v;
            v.x = Ts[(c4 * 4 + 0) * 68 + jr];
            v.y = Ts[(c4 * 4 + 1) * 68 + jr];
            v.z = Ts[(c4 * 4 + 2) * 68 + jr];
            v.w = Ts[(c4 * 4 + 3) * 68 + jr];
            *(float4*)&g_W[(j0 + jr) * NN + i0 + c4 * 4] = v;
        }
    }
}

// ---------------- K3: deg -> dis -> Z ------------------------------------
__global__ __launch_bounds__(256, 4)
void k3_degree() {
    const int i = blockIdx.x;
    const int t = threadIdx.x;
    float4 v = *(const float4*)&g_W[i * NN + t * 4];
    float s = v.x + v.y + v.z + v.w;
    #pragma unroll
    for (int o = 16; o > 0; o >>= 1) s += __shfl_down_sync(0xffffffffu, s, o);
    __shared__ float red[8];
    if ((t & 31) == 0) red[t >> 5] = s;
    __syncthreads();
    if (t < 32) {
        float r = (t < 8) ? red[t] : 0.f;
        #pragma unroll
        for (int o = 4; o > 0; o >>= 1) r += __shfl_down_sync(0xffffffffu, r, o);
        if (t == 0) red[0] = r;
    }
    __syncthreads();
    float dis = rsqrtf(red[0]);
    if (t == 0) g_dis[i] = dis;
    if (t < 128) g_z[i * HH + t] = dis * g_y[i * HH + t];
}

// ---------------- K4: split-K partials of W @ Z --------------------------
// grid (16, KSPLIT): 64-row blocks, k-range 128 (4 x BK=32).
// 256 threads: hq=t&31 -> h=hq*4, rq=t>>5 -> rows rq*8..+7 (warp-uniform W).
// 8x4 micro-tile: 1.5 B/FMA; W smem reads are warp broadcasts.
__global__ __launch_bounds__(256, 3)
void k4_aggregate() {
    const int i0 = blockIdx.x * 64;
    const int ks = blockIdx.y;
    const int t  = threadIdx.x;
    const int hq = t & 31;
    const int rq = t >> 5;
    const int h  = hq * 4;

    __shared__ float Zs[32][128];   // 16 KB
    __shared__ float Wst[32][68];   // transposed W tile (64 rows + pad)

    float4 acc[8];
    #pragma unroll
    for (int r = 0; r < 8; r++) acc[r] = make_float4(0.f, 0.f, 0.f, 0.f);

    #pragma unroll 1
    for (int c = 0; c < 4; c++) {
        const int k0 = ks * 128 + c * 32;
        #pragma unroll
        for (int p = 0; p < 4; p++) {
            int pos = t * 4 + p * 1024;
            int kk = pos >> 7, hh = pos & 127;
            *(float4*)&Zs[kk][hh] = *(const float4*)&g_z[(k0 + kk) * HH + hh];
        }
        #pragma unroll
        for (int p = 0; p < 2; p++) {
            int r = (t >> 3) + p * 32;
            int kkq = t & 7;
            float4 wv = *(const float4*)&g_W[(i0 + r) * NN + k0 + kkq * 4];
            Wst[kkq * 4 + 0][r] = wv.x;
            Wst[kkq * 4 + 1][r] = wv.y;
            Wst[kkq * 4 + 2][r] = wv.z;
            Wst[kkq * 4 + 3][r] = wv.w;
        }
        __syncthreads();
        #pragma unroll
        for (int kk = 0; kk < 32; kk++) {
            float4 zv = *(const float4*)&Zs[kk][h];
            float4 wa = *(const float4*)&Wst[kk][rq * 8];
            float4 wb = *(const float4*)&Wst[kk][rq * 8 + 4];
            acc[0].x = fmaf(wa.x, zv.x, acc[0].x);
            acc[0].y = fmaf(wa.x, zv.y, acc[0].y);
            acc[0].z = fmaf(wa.x, zv.z, acc[0].z);
            acc[0].w = fmaf(wa.x, zv.w, acc[0].w);
            acc[1].x = fmaf(wa.y, zv.x, acc[1].x);
            acc[1].y = fmaf(wa.y, zv.y, acc[1].y);
            acc[1].z = fmaf(wa.y, zv.z, acc[1].z);
            acc[1].w = fmaf(wa.y, zv.w, acc[1].w);
            acc[2].x = fmaf(wa.z, zv.x, acc[2].x);
            acc[2].y = fmaf(wa.z, zv.y, acc[2].y);
            acc[2].z = fmaf(wa.z, zv.z, acc[2].z);
            acc[2].w = fmaf(wa.z, zv.w, acc[2].w);
            acc[3].x = fmaf(wa.w, zv.x, acc[3].x);
            acc[3].y = fmaf(wa.w, zv.y, acc[3].y);
            acc[3].z = fmaf(wa.w, zv.z, acc[3].z);
            acc[3].w = fmaf(wa.w, zv.w, acc[3].w);
            acc[4].x = fmaf(wb.x, zv.x, acc[4].x);
            acc[4].y = fmaf(wb.x, zv.y, acc[4].y);
            acc[4].z = fmaf(wb.x, zv.z, acc[4].z);
            acc[4].w = fmaf(wb.x, zv.w, acc[4].w);
            acc[5].x = fmaf(wb.y, zv.x, acc[5].x);
            acc[5].y = fmaf(wb.y, zv.y, acc[5].y);
            acc[5].z = fmaf(wb.y, zv.z, acc[5].z);
            acc[5].w = fmaf(wb.y, zv.w, acc[5].w);
            acc[6].x = fmaf(wb.z, zv.x, acc[6].x);
            acc[6].y = fmaf(wb.z, zv.y, acc[6].y);
            acc[6].z = fmaf(wb.z, zv.z, acc[6].z);
            acc[6].w = fmaf(wb.z, zv.w, acc[6].w);
            acc[7].x = fmaf(wb.w, zv.x, acc[7].x);
            acc[7].y = fmaf(wb.w, zv.y, acc[7].y);
            acc[7].z = fmaf(wb.w, zv.z, acc[7].z);
            acc[7].w = fmaf(wb.w, zv.w, acc[7].w);
        }
        __syncthreads();
    }

    #pragma unroll
    for (int r = 0; r < 8; r++)
        *(float4*)&g_part[(ks * NN + i0 + rq * 8 + r) * HH + h] = acc[r];
}

// ---------------- K5: reduce partials + dis/bg epilogue + BN stats -------
__global__ __launch_bounds__(256, 4)
void k5_stats(const float* __restrict__ bg) {
    const int t = threadIdx.x;
    const int h = t & 127;
    const int half = t >> 7;
    const int ib = blockIdx.x * 16 + half * 8;
    const float bgv = bg[h];
    float s = 0.f, s2 = 0.f;
    #pragma unroll
    for (int r = 0; r < 8; r++) {
        int i = ib + r;
        int idx = i * HH + h;
        float v = 0.f;
        #pragma unroll
        for (int ks = 0; ks < KSPLIT; ks++) v += g_part[ks * NN * HH + idx];
        v = v * g_dis[i] + bgv;
        g_raw[idx] = v;
        s += v;
        s2 = fmaf(v, v, s2);
    }
    atomicAdd(&g_sum[h], s);
    atomicAdd(&g_sumsq[h], s2);
}

// ---------------- K6: normalize + relu -> d_out --------------------------
__global__ __launch_bounds__(256, 4)
void k6_norm(const float* __restrict__ gamma, const float* __restrict__ beta,
             float* __restrict__ out) {
    const int idx = blockIdx.x * 256 + threadIdx.x;
    const int h = idx & 127;
    const float inv_n = 1.f / (float)NN;
    float mean = g_sum[h] * inv_n;
    float var = g_sumsq[h] * inv_n - mean * mean;
    float x = g_raw[idx];
    float v = gamma[h] * (x - mean) * rsqrtf(var + BN_EPS) + beta[h];
    out[idx] = fmaxf(v, 0.f);
}

// ---------------- launch -------------------------------------------------
extern "C" void kernel_launch(void* const* d_in, const int* in_sizes, int n_in,
                              void* d_out, int out_size) {
    const float* X     = (const float*)d_in[0];
    const float* W1    = (const float*)d_in[1];
    const float* b1    = (const float*)d_in[2];
    const float* W2    = (const float*)d_in[3];
    const float* b2    = (const float*)d_in[4];
    const float* Wg    = (const float*)d_in[5];
    const float* bg    = (const float*)d_in[6];
    const float* gamma = (const float*)d_in[7];
    const float* beta  = (const float*)d_in[8];
    float* out = (float*)d_out;

    k1_gemm3<<<dim3(32, 3, KS1), 256>>>(X, W1, Wg);
    k1_reduce<<<384, 256>>>(b1);
    k2_pairwise<<<136, 256>>>(W2, b2);
    k3_degree<<<1024, 256>>>();
    k4_aggregate<<<dim3(16, KSPLIT), 256>>>();
    k5_stats<<<64, 256>>>(bg);
    k6_norm<<<512, 256>>>(gamma, beta, out);
}

// round 5
// speedup vs baseline: 1.4507x; 1.0392x over previous
#include <cuda_runtime.h>
#include <cuda_bf16.h>
#include <math.h>

#define NN   1024
#define DD   256
#define HH   128
#define KS1  4            // split-K for k1
#define KSPLIT 8          // split-K for k4
#define BN_EPS 1e-5f

// ---------------- scratch (device globals; no allocation) ----------------
__device__ float g_p1[3 * KS1 * NN * HH]; // k1 split-K partials (6 MB)
__device__ float g_a[NN * HH];            // X @ W1[:D] + b1
__device__ float g_c[NN * HH];            // X @ W1[D:]
__device__ float g_y[NN * HH];            // X @ Wg
__device__ float g_W[NN * NN];            // adjacency weights (symmetric, diag=1)
__device__ float g_deg[NN];               // degree (atomic accum from k2)
__device__ float g_dis[NN];               // rsqrt(deg)
__device__ float g_z[NN * HH];            // dis[j] * y[j]
__device__ float g_part[KSPLIT * NN * HH];// split-K partials of W@Z
__device__ float g_raw[NN * HH];          // dis[i]*(W@Z)[i] + bg  (pre-BN)
__device__ float g_sum[HH];
__device__ float g_sumsq[HH];

// packed f32x2 helpers
#define F2LL(x) (*reinterpret_cast<unsigned long long*>(&(x)))
__device__ __forceinline__ float2 fadd2(float2 a, float2 b) {
    float2 r;
    asm("add.rn.f32x2 %0, %1, %2;" : "=l"(F2LL(r)) : "l"(F2LL(a)), "l"(F2LL(b)));
    return r;
}
__device__ __forceinline__ void ffma2(float2& acc, float2 a, float2 b) {
    asm("fma.rn.f32x2 %0, %1, %2, %0;" : "+l"(F2LL(acc)) : "l"(F2LL(a)), "l"(F2LL(b)));
}
__device__ __forceinline__ float2 pack2(float v) {
    float2 r;
    asm("mov.b64 %0, {%1, %1};" : "=l"(F2LL(r)) : "f"(v));
    return r;
}

// ---------------- K1: split-K 3x GEMM partials (f32x2 packed) ------------
// grid (32, 3, KS1). 256 threads: hq=t&31 -> h=hq*4, rq=t>>5 -> rows rq*4..+3.
__global__ __launch_bounds__(256, 3)
void k1_gemm3(const float* __restrict__ X, const float* __restrict__ W1,
              const float* __restrict__ Wg) {
    const int z  = blockIdx.y;
    const int ks = blockIdx.z;
    const int i0 = blockIdx.x * 32;
    const int t  = threadIdx.x;
    const int hq = t & 31;
    const int rq = t >> 5;
    const int h  = hq * 4;

    if (z == 0 && ks == 0) {           // zero accumulators used later
        if (blockIdx.x == 0) {
            if (t < 128) g_sum[t] = 0.f;
            else g_sumsq[t - 128] = 0.f;
        } else if (blockIdx.x < 5) {
            g_deg[(blockIdx.x - 1) * 256 + t] = 0.f;
        }
    }

    const float* B = (z == 0) ? W1 : (z == 1) ? (W1 + DD * HH) : Wg;

    __shared__ float Bs[32][128];
    __shared__ float Xst[32][36];

    float2 accA[4], accB[4];
    #pragma unroll
    for (int r = 0; r < 4; r++) {
        accA[r] = make_float2(0.f, 0.f);
        accB[r] = make_float2(0.f, 0.f);
    }

    #pragma unroll
    for (int c = 0; c < 2; c++) {
        const int k0 = ks * 64 + c * 32;
        #pragma unroll
        for (int p = 0; p < 4; p++) {
            int pos = t * 4 + p * 1024;
            int kk = pos >> 7, hh = pos & 127;
            *(float4*)&Bs[kk][hh] = *(const float4*)&B[(k0 + kk) * HH + hh];
        }
        {
            int r = t >> 3, kkq = t & 7;
            float4 xv = *(const float4*)&X[(i0 + r) * DD + k0 + kkq * 4];
            Xst[kkq * 4 + 0][r] = xv.x;
            Xst[kkq * 4 + 1][r] = xv.y;
            Xst[kkq * 4 + 2][r] = xv.z;
            Xst[kkq * 4 + 3][r] = xv.w;
        }
        __syncthreads();
        #pragma unroll
        for (int kk = 0; kk < 32; kk++) {
            float4 b = *(const float4*)&Bs[kk][h];
            float2 b01 = make_float2(b.x, b.y);
            float2 b23 = make_float2(b.z, b.w);
            float4 x = *(const float4*)&Xst[kk][rq * 4];   // warp-uniform
            float xv[4] = {x.x, x.y, x.z, x.w};
            #pragma unroll
            for (int r = 0; r < 4; r++) {
                float2 wp = pack2(xv[r]);
                ffma2(accA[r], wp, b01);
                ffma2(accB[r], wp, b23);
            }
        }
        __syncthreads();
    }

    float* dst = g_p1 + (z * KS1 + ks) * (NN * HH);
    #pragma unroll
    for (int r = 0; r < 4; r++) {
        float4 v = make_float4(accA[r].x, accA[r].y, accB[r].x, accB[r].y);
        *(float4*)&dst[(i0 + rq * 4 + r) * HH + h] = v;
    }
}

// ---------------- K1R: reduce k1 partials (+b1 into g_a) -----------------
__global__ __launch_bounds__(256, 4)
void k1_reduce(const float* __restrict__ b1) {
    const int f = blockIdx.x * 256 + threadIdx.x;
    const int z = f >> 15;
    const int r = f & 32767;
    const float4* p = (const float4*)g_p1;
    float4 v = p[(z * KS1 + 0) * 32768 + r];
    #pragma unroll
    for (int ks = 1; ks < KS1; ks++) {
        float4 u = p[(z * KS1 + ks) * 32768 + r];
        v.x += u.x; v.y += u.y; v.z += u.z; v.w += u.w;
    }
    if (z == 0) {
        int h0 = (r * 4) & 127;
        v.x += b1[h0]; v.y += b1[h0 + 1]; v.z += b1[h0 + 2]; v.w += b1[h0 + 3];
    }
    float* dst = (z == 0) ? g_a : (z == 1) ? g_c : g_y;
    *(float4*)&dst[r * 4] = v;
}

// ---------------- K2: pairwise sim + degree accumulation -----------------
// 136 blocks, 256 threads, 4x4 f32x2 register tile; coalesced dual-triangle
// stores from an smem-staged tile; degree row/col sums folded into the
// store passes via shuffle-reduce + atomicAdd.
__global__ __launch_bounds__(256, 1)
void k2_pairwise(const float* __restrict__ W2, const float* __restrict__ b2) {
    int rem = blockIdx.x;
    int ti = 0;
    #pragma unroll 1
    while (rem >= (16 - ti)) { rem -= (16 - ti); ti++; }
    const int tj = ti + rem;
    const int i0 = ti * 64, j0 = tj * 64;
    const int t = threadIdx.x;

    __shared__ float2 As2[64 * 65];
    __shared__ float2 Cs2[64 * 65];
    __shared__ float2 W2s2[64];

    if (t < 64) W2s2[t] = ((const float2*)W2)[t];
    const float2* ga2 = (const float2*)g_a;
    const float2* gc2 = (const float2*)g_c;
    #pragma unroll
    for (int p = 0; p < 16; p++) {
        int idx = t + p * 256;
        int row = idx >> 6, h2 = idx & 63;
        As2[row * 65 + h2] = ga2[(i0 + row) * 64 + h2];
        Cs2[row * 65 + h2] = gc2[(j0 + row) * 64 + h2];
    }
    __syncthreads();

    const int iq = t >> 4;
    const int jq = t & 15;

    float2 acc[4][4];
    #pragma unroll
    for (int r = 0; r < 4; r++)
        #pragma unroll
        for (int s = 0; s < 4; s++) acc[r][s] = make_float2(0.f, 0.f);

    #pragma unroll 4
    for (int h2 = 0; h2 < 64; h2++) {
        float2 w = W2s2[h2];
        float2 a[4], c[4];
        #pragma unroll
        for (int r = 0; r < 4; r++) a[r] = As2[(iq + r * 16) * 65 + h2];
        #pragma unroll
        for (int s = 0; s < 4; s++) c[s] = Cs2[(jq + s * 16) * 65 + h2];
        #pragma unroll
        for (int r = 0; r < 4; r++) {
            #pragma unroll
            for (int s = 0; s < 4; s++) {
                float2 v = fadd2(a[r], c[s]);
                v.x = fmaxf(v.x, 0.f);
                v.y = fmaxf(v.y, 0.f);
                ffma2(acc[r][s], v, w);
            }
        }
    }

    __syncthreads();
    float* Ts = (float*)As2;        // staged tile [64][68]
    const float b2v = b2[0];
    const bool diag = (ti == tj);
    #pragma unroll
    for (int r = 0; r < 4; r++) {
        #pragma unroll
        for (int s = 0; s < 4; s++) {
            int il = iq + r * 16;
            int jl = jq + s * 16;
            float x = acc[r][s].x + acc[r][s].y + b2v;
            float sg = 1.f / (1.f + __expf(-x));
            float w = (x > 0.f) ? sg : 0.f;
            if (!diag) {
                Ts[il * 68 + jl] = w;
            } else {
                if (il < jl) {
                    Ts[il * 68 + jl] = w;
                    Ts[jl * 68 + il] = w;
                } else if (il == jl) {
                    Ts[il * 68 + il] = 1.0f;
                }
            }
        }
    }
    __syncthreads();

    // pass 1: rows i0.., cols j0.. (coalesced) + row-degree contributions
    #pragma unroll
    for (int p = 0; p < 4; p++) {
        int idx = t + p * 256;
        int row = idx >> 4, c4 = idx & 15;
        float4 v = *(const float4*)&Ts[row * 68 + c4 * 4];
        *(float4*)&g_W[(i0 + row) * NN + j0 + c4 * 4] = v;
        float s = (v.x + v.y) + (v.z + v.w);
        #pragma unroll
        for (int o = 8; o > 0; o >>= 1) s += __shfl_down_sync(0xffffffffu, s, o, 16);
        if (c4 == 0) atomicAdd(&g_deg[i0 + row], s);
    }
    // pass 2 (off-diag): transposed triangle + col-degree contributions
    if (!diag) {
        #pragma unroll
        for (int p = 0; p < 4; p++) {
            int idx = t + p * 256;
            int jr = idx >> 4, c4 = idx & 15;
            float4 v;
            v.x = Ts[(c4 * 4 + 0) * 68 + jr];
            v.y = Ts[(c4 * 4 + 1) * 68 + jr];
            v.z = Ts[(c4 * 4 + 2) * 68 + jr];
            v.w = Ts[(c4 * 4 + 3) * 68 + jr];
            *(float4*)&g_W[(j0 + jr) * NN + i0 + c4 * 4] = v;
            float s = (v.x + v.y) + (v.z + v.w);
            #pragma unroll
            for (int o = 8; o > 0; o >>= 1) s += __shfl_down_sync(0xffffffffu, s, o, 16);
            if (c4 == 0) atomicAdd(&g_deg[j0 + jr], s);
        }
    }
}

// ---------------- K3: dis = rsqrt(deg); Z = dis * Y ----------------------
__global__ __launch_bounds__(256, 4)
void k3_dis() {
    const int idx = blockIdx.x * 256 + threadIdx.x;   // float4 index 0..32767
    const int i  = idx >> 5;
    const int h4 = idx & 31;
    float dis = rsqrtf(g_deg[i]);
    if (h4 == 0) g_dis[i] = dis;
    float4 y = ((const float4*)g_y)[idx];
    y.x *= dis; y.y *= dis; y.z *= dis; y.w *= dis;
    ((float4*)g_z)[idx] = y;
}

// ---------------- K4: split-K partials of W @ Z (f32x2 packed) -----------
// grid (16, KSPLIT): 64-row blocks, k-range 128 (4 x BK=32).
// 8x4 micro-tile; W smem reads are warp broadcasts.
__global__ __launch_bounds__(256, 3)
void k4_aggregate() {
    const int i0 = blockIdx.x * 64;
    const int ks = blockIdx.y;
    const int t  = threadIdx.x;
    const int hq = t & 31;
    const int rq = t >> 5;
    const int h  = hq * 4;

    __shared__ float Zs[32][128];
    __shared__ float Wst[32][68];

    float2 accA[8], accB[8];
    #pragma unroll
    for (int r = 0; r < 8; r++) {
        accA[r] = make_float2(0.f, 0.f);
        accB[r] = make_float2(0.f, 0.f);
    }

    #pragma unroll 1
    for (int c = 0; c < 4; c++) {
        const int k0 = ks * 128 + c * 32;
        #pragma unroll
        for (int p = 0; p < 4; p++) {
            int pos = t * 4 + p * 1024;
            int kk = pos >> 7, hh = pos & 127;
            *(float4*)&Zs[kk][hh] = *(const float4*)&g_z[(k0 + kk) * HH + hh];
        }
        #pragma unroll
        for (int p = 0; p < 2; p++) {
            int r = (t >> 3) + p * 32;
            int kkq = t & 7;
            float4 wv = *(const float4*)&g_W[(i0 + r) * NN + k0 + kkq * 4];
            Wst[kkq * 4 + 0][r] = wv.x;
            Wst[kkq * 4 + 1][r] = wv.y;
            Wst[kkq * 4 + 2][r] = wv.z;
            Wst[kkq * 4 + 3][r] = wv.w;
        }
        __syncthreads();
        #pragma unroll
        for (int kk = 0; kk < 32; kk++) {
            float4 zv = *(const float4*)&Zs[kk][h];
            float2 z01 = make_float2(zv.x, zv.y);
            float2 z23 = make_float2(zv.z, zv.w);
            float4 wa = *(const float4*)&Wst[kk][rq * 8];      // broadcast
            float4 wb = *(const float4*)&Wst[kk][rq * 8 + 4];  // broadcast
            float wv[8] = {wa.x, wa.y, wa.z, wa.w, wb.x, wb.y, wb.z, wb.w};
            #pragma unroll
            for (int r = 0; r < 8; r++) {
                float2 wp = pack2(wv[r]);
                ffma2(accA[r], wp, z01);
                ffma2(accB[r], wp, z23);
            }
        }
        __syncthreads();
    }

    #pragma unroll
    for (int r = 0; r < 8; r++) {
        float4 v = make_float4(accA[r].x, accA[r].y, accB[r].x, accB[r].y);
        *(float4*)&g_part[(ks * NN + i0 + rq * 8 + r) * HH + h] = v;
    }
}

// ---------------- K5: reduce partials + dis/bg epilogue + BN stats -------
__global__ __launch_bounds__(256, 4)
void k5_stats(const float* __restrict__ bg) {
    const int t = threadIdx.x;
    const int h = t & 127;
    const int half = t >> 7;
    const int ib = blockIdx.x * 16 + half * 8;
    const float bgv = bg[h];
    float s = 0.f, s2 = 0.f;
    #pragma unroll
    for (int r = 0; r < 8; r++) {
        int i = ib + r;
        int idx = i * HH + h;
        float v = 0.f;
        #pragma unroll
        for (int ks = 0; ks < KSPLIT; ks++) v += g_part[ks * NN * HH + idx];
        v = v * g_dis[i] + bgv;
        g_raw[idx] = v;
        s += v;
        s2 = fmaf(v, v, s2);
    }
    atomicAdd(&g_sum[h], s);
    atomicAdd(&g_sumsq[h], s2);
}

// ---------------- K6: normalize + relu -> d_out --------------------------
__global__ __launch_bounds__(256, 4)
void k6_norm(const float* __restrict__ gamma, const float* __restrict__ beta,
             float* __restrict__ out) {
    const int idx = blockIdx.x * 256 + threadIdx.x;
    const int h = idx & 127;
    const float inv_n = 1.f / (float)NN;
    float mean = g_sum[h] * inv_n;
    float var = g_sumsq[h] * inv_n - mean * mean;
    float x = g_raw[idx];
    float v = gamma[h] * (x - mean) * rsqrtf(var + BN_EPS) + beta[h];
    out[idx] = fmaxf(v, 0.f);
}

// ---------------- launch -------------------------------------------------
extern "C" void kernel_launch(void* const* d_in, const int* in_sizes, int n_in,
                              void* d_out, int out_size) {
    const float* X     = (const float*)d_in[0];
    const float* W1    = (const float*)d_in[1];
    const float* b1    = (const float*)d_in[2];
    const float* W2    = (const float*)d_in[3];
    const float* b2    = (const float*)d_in[4];
    const float* Wg    = (const float*)d_in[5];
    const float* bg    = (const float*)d_in[6];
    const float* gamma = (const float*)d_in[7];
    const float* beta  = (const float*)d_in[8];
    float* out = (float*)d_out;

    k1_gemm3<<<dim3(32, 3, KS1), 256>>>(X, W1, Wg);
    k1_reduce<<<384, 256>>>(b1);
    k2_pairwise<<<136, 256>>>(W2, b2);
    k3_dis<<<128, 256>>>();
    k4_aggregate<<<dim3(16, KSPLIT), 256>>>();
    k5_stats<<<64, 256>>>(bg);
    k6_norm<<<512, 256>>>(gamma, beta, out);
}

// round 6
// speedup vs baseline: 1.4613x; 1.0073x over previous
#include <cuda_runtime.h>
#include <cuda_bf16.h>
#include <math.h>

#define NN   1024
#define DD   256
#define HH   128
#define KSPLIT 8          // split-K for k4
#define BN_EPS 1e-5f

// ---------------- scratch (device globals; no allocation) ----------------
__device__ float g_a[NN * HH];            // X @ W1[:D] + b1
__device__ float g_c[NN * HH];            // X @ W1[D:]
__device__ float g_y[NN * HH];            // X @ Wg
__device__ float g_W[NN * NN];            // adjacency weights (symmetric, diag=1)
__device__ float g_deg[NN];               // degree (atomic accum from k2)
__device__ float g_part[KSPLIT * NN * HH];// split-K partials of W@Z
__device__ float g_raw[NN * HH];          // dis[i]*(W@Z)[i] + bg  (pre-BN)
__device__ float g_sum[HH];
__device__ float g_sumsq[HH];

// packed f32x2 helpers
#define F2LL(x) (*reinterpret_cast<unsigned long long*>(&(x)))
__device__ __forceinline__ float2 fadd2(float2 a, float2 b) {
    float2 r;
    asm("add.rn.f32x2 %0, %1, %2;" : "=l"(F2LL(r)) : "l"(F2LL(a)), "l"(F2LL(b)));
    return r;
}
__device__ __forceinline__ void ffma2(float2& acc, float2 a, float2 b) {
    asm("fma.rn.f32x2 %0, %1, %2, %0;" : "+l"(F2LL(acc)) : "l"(F2LL(a)), "l"(F2LL(b)));
}
__device__ __forceinline__ float2 pack2(float v) {
    float2 r;
    asm("mov.b64 %0, {%1, %1};" : "=l"(F2LL(r)) : "f"(v));
    return r;
}

// ---------------- K1: direct 3x GEMM  C[1024,128] = X @ B[256,128] -------
// grid (32, 3): 32-row blocks, z selects {W1a(+b1), W1c, Wg}. Full K=256.
// 256 threads: hq=t&31 -> h=hq*4, rq=t>>5 -> rows rq*4..+3 (4x4 micro).
__global__ __launch_bounds__(256, 3)
void k1_gemm3(const float* __restrict__ X, const float* __restrict__ W1,
              const float* __restrict__ Wg, const float* __restrict__ b1) {
    const int z  = blockIdx.y;
    const int i0 = blockIdx.x * 32;
    const int t  = threadIdx.x;
    const int hq = t & 31;
    const int rq = t >> 5;
    const int h  = hq * 4;

    if (z == 0) {                       // zero accumulators used later
        if (blockIdx.x == 0) {
            if (t < 128) g_sum[t] = 0.f;
            else g_sumsq[t - 128] = 0.f;
        } else if (blockIdx.x < 5) {
            g_deg[(blockIdx.x - 1) * 256 + t] = 0.f;
        }
    }

    const float* B = (z == 0) ? W1 : (z == 1) ? (W1 + DD * HH) : Wg;

    __shared__ float Bs[32][128];
    __shared__ float Xst[32][36];

    float2 accA[4], accB[4];
    #pragma unroll
    for (int r = 0; r < 4; r++) {
        accA[r] = make_float2(0.f, 0.f);
        accB[r] = make_float2(0.f, 0.f);
    }

    #pragma unroll 1
    for (int c = 0; c < 8; c++) {
        const int k0 = c * 32;
        #pragma unroll
        for (int p = 0; p < 4; p++) {
            int pos = t * 4 + p * 1024;
            int kk = pos >> 7, hh = pos & 127;
            *(float4*)&Bs[kk][hh] = *(const float4*)&B[(k0 + kk) * HH + hh];
        }
        {
            int r = t >> 3, kkq = t & 7;
            float4 xv = *(const float4*)&X[(i0 + r) * DD + k0 + kkq * 4];
            Xst[kkq * 4 + 0][r] = xv.x;
            Xst[kkq * 4 + 1][r] = xv.y;
            Xst[kkq * 4 + 2][r] = xv.z;
            Xst[kkq * 4 + 3][r] = xv.w;
        }
        __syncthreads();
        #pragma unroll
        for (int kk = 0; kk < 32; kk++) {
            float4 b = *(const float4*)&Bs[kk][h];
            float2 b01 = make_float2(b.x, b.y);
            float2 b23 = make_float2(b.z, b.w);
            float4 x = *(const float4*)&Xst[kk][rq * 4];   // warp-uniform
            float xv[4] = {x.x, x.y, x.z, x.w};
            #pragma unroll
            for (int r = 0; r < 4; r++) {
                float2 wp = pack2(xv[r]);
                ffma2(accA[r], wp, b01);
                ffma2(accB[r], wp, b23);
            }
        }
        __syncthreads();
    }

    float bias0 = 0.f, bias1 = 0.f, bias2 = 0.f, bias3 = 0.f;
    if (z == 0) {
        float4 bv = *(const float4*)&b1[h];
        bias0 = bv.x; bias1 = bv.y; bias2 = bv.z; bias3 = bv.w;
    }
    float* dst = (z == 0) ? g_a : (z == 1) ? g_c : g_y;
    #pragma unroll
    for (int r = 0; r < 4; r++) {
        float4 v = make_float4(accA[r].x + bias0, accA[r].y + bias1,
                               accB[r].x + bias2, accB[r].y + bias3);
        *(float4*)&dst[(i0 + rq * 4 + r) * HH + h] = v;
    }
}

// ---------------- K2: pairwise sim + degree accumulation -----------------
// 136 blocks, 256 threads, 4x4 f32x2 register tile; coalesced dual-triangle
// stores from an smem-staged tile; degree row/col sums folded into the
// store passes via shuffle-reduce + atomicAdd.
__global__ __launch_bounds__(256, 1)
void k2_pairwise(const float* __restrict__ W2, const float* __restrict__ b2) {
    int rem = blockIdx.x;
    int ti = 0;
    #pragma unroll 1
    while (rem >= (16 - ti)) { rem -= (16 - ti); ti++; }
    const int tj = ti + rem;
    const int i0 = ti * 64, j0 = tj * 64;
    const int t = threadIdx.x;

    __shared__ float2 As2[64 * 65];
    __shared__ float2 Cs2[64 * 65];
    __shared__ float2 W2s2[64];

    if (t < 64) W2s2[t] = ((const float2*)W2)[t];
    const float2* ga2 = (const float2*)g_a;
    const float2* gc2 = (const float2*)g_c;
    #pragma unroll
    for (int p = 0; p < 16; p++) {
        int idx = t + p * 256;
        int row = idx >> 6, h2 = idx & 63;
        As2[row * 65 + h2] = ga2[(i0 + row) * 64 + h2];
        Cs2[row * 65 + h2] = gc2[(j0 + row) * 64 + h2];
    }
    __syncthreads();

    const int iq = t >> 4;
    const int jq = t & 15;

    float2 acc[4][4];
    #pragma unroll
    for (int r = 0; r < 4; r++)
        #pragma unroll
        for (int s = 0; s < 4; s++) acc[r][s] = make_float2(0.f, 0.f);

    #pragma unroll 4
    for (int h2 = 0; h2 < 64; h2++) {
        float2 w = W2s2[h2];
        float2 a[4], c[4];
        #pragma unroll
        for (int r = 0; r < 4; r++) a[r] = As2[(iq + r * 16) * 65 + h2];
        #pragma unroll
        for (int s = 0; s < 4; s++) c[s] = Cs2[(jq + s * 16) * 65 + h2];
        #pragma unroll
        for (int r = 0; r < 4; r++) {
            #pragma unroll
            for (int s = 0; s < 4; s++) {
                float2 v = fadd2(a[r], c[s]);
                v.x = fmaxf(v.x, 0.f);
                v.y = fmaxf(v.y, 0.f);
                ffma2(acc[r][s], v, w);
            }
        }
    }

    __syncthreads();
    float* Ts = (float*)As2;        // staged tile [64][68]
    const float b2v = b2[0];
    const bool diag = (ti == tj);
    #pragma unroll
    for (int r = 0; r < 4; r++) {
        #pragma unroll
        for (int s = 0; s < 4; s++) {
            int il = iq + r * 16;
            int jl = jq + s * 16;
            float x = acc[r][s].x + acc[r][s].y + b2v;
            float sg = 1.f / (1.f + __expf(-x));
            float w = (x > 0.f) ? sg : 0.f;
            if (!diag) {
                Ts[il * 68 + jl] = w;
            } else {
                if (il < jl) {
                    Ts[il * 68 + jl] = w;
                    Ts[jl * 68 + il] = w;
                } else if (il == jl) {
                    Ts[il * 68 + il] = 1.0f;
                }
            }
        }
    }
    __syncthreads();

    // pass 1: rows i0.., cols j0.. (coalesced) + row-degree contributions
    #pragma unroll
    for (int p = 0; p < 4; p++) {
        int idx = t + p * 256;
        int row = idx >> 4, c4 = idx & 15;
        float4 v = *(const float4*)&Ts[row * 68 + c4 * 4];
        *(float4*)&g_W[(i0 + row) * NN + j0 + c4 * 4] = v;
        float s = (v.x + v.y) + (v.z + v.w);
        #pragma unroll
        for (int o = 8; o > 0; o >>= 1) s += __shfl_down_sync(0xffffffffu, s, o, 16);
        if (c4 == 0) atomicAdd(&g_deg[i0 + row], s);
    }
    // pass 2 (off-diag): transposed triangle + col-degree contributions
    if (!diag) {
        #pragma unroll
        for (int p = 0; p < 4; p++) {
            int idx = t + p * 256;
            int jr = idx >> 4, c4 = idx & 15;
            float4 v;
            v.x = Ts[(c4 * 4 + 0) * 68 + jr];
            v.y = Ts[(c4 * 4 + 1) * 68 + jr];
            v.z = Ts[(c4 * 4 + 2) * 68 + jr];
            v.w = Ts[(c4 * 4 + 3) * 68 + jr];
            *(float4*)&g_W[(j0 + jr) * NN + i0 + c4 * 4] = v;
            float s = (v.x + v.y) + (v.z + v.w);
            #pragma unroll
            for (int o = 8; o > 0; o >>= 1) s += __shfl_down_sync(0xffffffffu, s, o, 16);
            if (c4 == 0) atomicAdd(&g_deg[j0 + jr], s);
        }
    }
}

// ---------------- K4: split-K partials of W @ Z, dis folded on load ------
// grid (16, KSPLIT): 64-row blocks, k-range 128 (4 x BK=32).
// Z tile built on the fly: Zs[kk][h] = rsqrt(deg[k]) * y[k][h].
__global__ __launch_bounds__(256, 3)
void k4_aggregate() {
    const int i0 = blockIdx.x * 64;
    const int ks = blockIdx.y;
    const int t  = threadIdx.x;
    const int hq = t & 31;
    const int rq = t >> 5;
    const int h  = hq * 4;

    __shared__ float Zs[32][128];
    __shared__ float Wst[32][68];

    float2 accA[8], accB[8];
    #pragma unroll
    for (int r = 0; r < 8; r++) {
        accA[r] = make_float2(0.f, 0.f);
        accB[r] = make_float2(0.f, 0.f);
    }

    #pragma unroll 1
    for (int c = 0; c < 4; c++) {
        const int k0 = ks * 128 + c * 32;
        #pragma unroll
        for (int p = 0; p < 4; p++) {
            int pos = t * 4 + p * 1024;
            int kk = pos >> 7, hh = pos & 127;
            float dis = rsqrtf(g_deg[k0 + kk]);
            float4 y = *(const float4*)&g_y[(k0 + kk) * HH + hh];
            y.x *= dis; y.y *= dis; y.z *= dis; y.w *= dis;
            *(float4*)&Zs[kk][hh] = y;
        }
        #pragma unroll
        for (int p = 0; p < 2; p++) {
            int r = (t >> 3) + p * 32;
            int kkq = t & 7;
            float4 wv = *(const float4*)&g_W[(i0 + r) * NN + k0 + kkq * 4];
            Wst[kkq * 4 + 0][r] = wv.x;
            Wst[kkq * 4 + 1][r] = wv.y;
            Wst[kkq * 4 + 2][r] = wv.z;
            Wst[kkq * 4 + 3][r] = wv.w;
        }
        __syncthreads();
        #pragma unroll
        for (int kk = 0; kk < 32; kk++) {
            float4 zv = *(const float4*)&Zs[kk][h];
            float2 z01 = make_float2(zv.x, zv.y);
            float2 z23 = make_float2(zv.z, zv.w);
            float4 wa = *(const float4*)&Wst[kk][rq * 8];      // broadcast
            float4 wb = *(const float4*)&Wst[kk][rq * 8 + 4];  // broadcast
            float wv[8] = {wa.x, wa.y, wa.z, wa.w, wb.x, wb.y, wb.z, wb.w};
            #pragma unroll
            for (int r = 0; r < 8; r++) {
                float2 wp = pack2(wv[r]);
                ffma2(accA[r], wp, z01);
                ffma2(accB[r], wp, z23);
            }
        }
        __syncthreads();
    }

    #pragma unroll
    for (int r = 0; r < 8; r++) {
        float4 v = make_float4(accA[r].x, accA[r].y, accB[r].x, accB[r].y);
        *(float4*)&g_part[(ks * NN + i0 + rq * 8 + r) * HH + h] = v;
    }
}

// ---------------- K5: reduce partials + dis/bg epilogue + BN stats -------
__global__ __launch_bounds__(256, 4)
void k5_stats(const float* __restrict__ bg) {
    const int t = threadIdx.x;
    const int h = t & 127;
    const int half = t >> 7;
    const int ib = blockIdx.x * 8 + half * 4;
    const float bgv = bg[h];
    float s = 0.f, s2 = 0.f;
    #pragma unroll
    for (int r = 0; r < 4; r++) {
        int i = ib + r;
        int idx = i * HH + h;
        float v = 0.f;
        #pragma unroll
        for (int ks = 0; ks < KSPLIT; ks++) v += g_part[ks * NN * HH + idx];
        v = v * rsqrtf(g_deg[i]) + bgv;
        g_raw[idx] = v;
        s += v;
        s2 = fmaf(v, v, s2);
    }
    atomicAdd(&g_sum[h], s);
    atomicAdd(&g_sumsq[h], s2);
}

// ---------------- K6: normalize + relu -> d_out (float4) -----------------
__global__ __launch_bounds__(256, 4)
void k6_norm(const float* __restrict__ gamma, const float* __restrict__ beta,
             float* __restrict__ out) {
    const int idx = blockIdx.x * 256 + threadIdx.x;   // float4 idx 0..32767
    const int h4 = (idx & 31) * 4;
    const float inv_n = 1.f / (float)NN;
    float4 sm = *(const float4*)&g_sum[h4];
    float4 sq = *(const float4*)&g_sumsq[h4];
    float4 gm = *(const float4*)&gamma[h4];
    float4 bt = *(const float4*)&beta[h4];
    float4 x = ((const float4*)g_raw)[idx];
    float m, vv, sc;
    m = sm.x * inv_n; vv = sq.x * inv_n - m * m; sc = gm.x * rsqrtf(vv + BN_EPS);
    x.x = fmaxf((x.x - m) * sc + bt.x, 0.f);
    m = sm.y * inv_n; vv = sq.y * inv_n - m * m; sc = gm.y * rsqrtf(vv + BN_EPS);
    x.y = fmaxf((x.y - m) * sc + bt.y, 0.f);
    m = sm.z * inv_n; vv = sq.z * inv_n - m * m; sc = gm.z * rsqrtf(vv + BN_EPS);
    x.z = fmaxf((x.z - m) * sc + bt.z, 0.f);
    m = sm.w * inv_n; vv = sq.w * inv_n - m * m; sc = gm.w * rsqrtf(vv + BN_EPS);
    x.w = fmaxf((x.w - m) * sc + bt.w, 0.f);
    ((float4*)out)[idx] = x;
}

// ---------------- launch -------------------------------------------------
extern "C" void kernel_launch(void* const* d_in, const int* in_sizes, int n_in,
                              void* d_out, int out_size) {
    const float* X     = (const float*)d_in[0];
    const float* W1    = (const float*)d_in[1];
    const float* b1    = (const float*)d_in[2];
    const float* W2    = (const float*)d_in[3];
    const float* b2    = (const float*)d_in[4];
    const float* Wg    = (const float*)d_in[5];
    const float* bg    = (const float*)d_in[6];
    const float* gamma = (const float*)d_in[7];
    const float* beta  = (const float*)d_in[8];
    float* out = (float*)d_out;

    k1_gemm3<<<dim3(32, 3), 256>>>(X, W1, Wg, b1);
    k2_pairwise<<<136, 256>>>(W2, b2);
    k4_aggregate<<<dim3(16, KSPLIT), 256>>>();
    k5_stats<<<128, 256>>>(bg);
    k6_norm<<<128, 256>>>(gamma, beta, out);
}